// round 5
// baseline (speedup 1.0000x reference)
#include <cuda_runtime.h>

#define N_H_NODES 50000
#define N_G_NODES 50000
#define N_X 64
#define N_H 64
#define N_GC 128
#define N_U 64
#define D_EDGE 128
#define D_NODE_IN 320

// Scatter-sum accumulator: 50000 x 128 floats = 25.6 MB static device scratch.
// 128B-aligned: accessed via float4 (128-bit) loads/stores.
__device__ __align__(128) float g_accum[(size_t)N_G_NODES * N_GC];

__device__ __forceinline__ float lrelu(float v) {
    return v >= 0.0f ? v : 0.1f * v;
}

// ---------------------------------------------------------------------------
// Zero the accumulator (must run before edge kernel each launch)
// ---------------------------------------------------------------------------
__global__ void zero_accum_kernel() {
    size_t n4 = (size_t)N_G_NODES * N_GC / 4;
    float4 z = make_float4(0.f, 0.f, 0.f, 0.f);
    float4* p = reinterpret_cast<float4*>(g_accum);
    for (size_t i = (size_t)blockIdx.x * blockDim.x + threadIdx.x; i < n4;
         i += (size_t)gridDim.x * blockDim.x)
        p[i] = z;
}

// ---------------------------------------------------------------------------
// Edge kernel: per 128-edge tile,
//   V[i] = [x_h[src[i]] (64), edge_attr[i] (64)]     (SMEM, 128 floats/row)
//   H = leaky(V @ W1a^T + b1a);  O = H @ W1b^T + b1b
//   atomicAdd O rows into g_accum[tgt[i]]
// Persistent blocks; W1a_t/W1b_t resident in SMEM.
// Per thread: 8 edges x 4 output cols.
// ---------------------------------------------------------------------------
#define ET   128
#define ETH  512

#define EO_WA   0
#define EO_WB   16384
#define EO_V    32768
#define EO_B1A  49152
#define EO_B1B  49280
#define EO_IDX  49408
#define E_SMEM_BYTES ((49408 + 2 * ET) * 4)

__global__ void __launch_bounds__(ETH, 1)
edge_kernel(const float* __restrict__ x_h,
            const float* __restrict__ edge_attr,
            const float* __restrict__ W1a, const float* __restrict__ b1a,
            const float* __restrict__ W1b, const float* __restrict__ b1b,
            const int* __restrict__ eidx, int E)
{
    extern __shared__ float sm[];
    float* Wa   = sm + EO_WA;
    float* Wb   = sm + EO_WB;
    float* V    = sm + EO_V;
    float* sb1a = sm + EO_B1A;
    float* sb1b = sm + EO_B1B;
    int*   s_src = reinterpret_cast<int*>(sm + EO_IDX);
    int*   s_tgt = s_src + ET;

    const int tid = threadIdx.x;

    for (int t = tid; t < 128 * 128; t += ETH) {
        int j = t >> 7, k = t & 127;
        Wa[k * 128 + j] = W1a[t];
        Wb[k * 128 + j] = W1b[t];
    }
    if (tid < 128) { sb1a[tid] = b1a[tid]; sb1b[tid] = b1b[tid]; }
    __syncthreads();

    const float4* Wa4 = reinterpret_cast<const float4*>(Wa);
    const float4* Wb4 = reinterpret_cast<const float4*>(Wb);
    float4* V4 = reinterpret_cast<float4*>(V);
    const int* srcp = eidx;       // edge_index row 0 (int32)
    const int* tgtp = eidx + E;   // edge_index row 1 (int32)

    const int w = tid >> 5;
    const int l = tid & 31;
    const int i0 = w * 8;
    const float4 bias_a = reinterpret_cast<const float4*>(sb1a)[l];
    const float4 bias_b = reinterpret_cast<const float4*>(sb1b)[l];

    const int numTiles = (E + ET - 1) / ET;
    for (int tile = blockIdx.x; tile < numTiles; tile += gridDim.x) {
        const int e0 = tile * ET;
        __syncthreads();

        if (tid < ET) {
            int e = e0 + tid;
            int s = 0, t = -1;
            if (e < E) {
                s = srcp[e];
                t = tgtp[e];
                // Defensive clamp: garbage index -> wrong answer, not a trap.
                if (s < 0) s = 0;
                if (s >= N_H_NODES) s = N_H_NODES - 1;
                if (t < 0 || t >= N_G_NODES) t = -1;
            }
            s_src[tid] = s;
            s_tgt[tid] = t;
        }
        __syncthreads();

        // Gather: V row = [x_h[src] | edge_attr]
        for (int f = tid; f < ET * 32; f += ETH) {
            int i = f >> 5, c = f & 31;
            int e = e0 + i;
            float4 val = make_float4(0.f, 0.f, 0.f, 0.f);
            if (e < E) {
                if (c < 16)
                    val = reinterpret_cast<const float4*>(x_h)[(size_t)s_src[i] * 16 + c];
                else
                    val = reinterpret_cast<const float4*>(edge_attr)[(size_t)e * 16 + (c - 16)];
            }
            V4[f] = val;
        }
        __syncthreads();

        // --- GEMM 1: H = leaky(V @ W1a^T + b1a) ---
        float4 acc[8];
        #pragma unroll
        for (int i = 0; i < 8; ++i) acc[i] = bias_a;

        for (int k4 = 0; k4 < 32; ++k4) {
            float4 w0 = Wa4[(k4 * 4 + 0) * 32 + l];
            float4 w1 = Wa4[(k4 * 4 + 1) * 32 + l];
            float4 w2 = Wa4[(k4 * 4 + 2) * 32 + l];
            float4 w3 = Wa4[(k4 * 4 + 3) * 32 + l];
            #pragma unroll
            for (int i = 0; i < 8; ++i) {
                float4 v = V4[(i0 + i) * 32 + k4];
                acc[i].x = fmaf(v.x, w0.x, acc[i].x);
                acc[i].y = fmaf(v.x, w0.y, acc[i].y);
                acc[i].z = fmaf(v.x, w0.z, acc[i].z);
                acc[i].w = fmaf(v.x, w0.w, acc[i].w);
                acc[i].x = fmaf(v.y, w1.x, acc[i].x);
                acc[i].y = fmaf(v.y, w1.y, acc[i].y);
                acc[i].z = fmaf(v.y, w1.z, acc[i].z);
                acc[i].w = fmaf(v.y, w1.w, acc[i].w);
                acc[i].x = fmaf(v.z, w2.x, acc[i].x);
                acc[i].y = fmaf(v.z, w2.y, acc[i].y);
                acc[i].z = fmaf(v.z, w2.z, acc[i].z);
                acc[i].w = fmaf(v.z, w2.w, acc[i].w);
                acc[i].x = fmaf(v.w, w3.x, acc[i].x);
                acc[i].y = fmaf(v.w, w3.y, acc[i].y);
                acc[i].z = fmaf(v.w, w3.z, acc[i].z);
                acc[i].w = fmaf(v.w, w3.w, acc[i].w);
            }
        }

        __syncwarp();
        #pragma unroll
        for (int i = 0; i < 8; ++i) {
            float4 h;
            h.x = lrelu(acc[i].x); h.y = lrelu(acc[i].y);
            h.z = lrelu(acc[i].z); h.w = lrelu(acc[i].w);
            V4[(i0 + i) * 32 + l] = h;
        }
        __syncwarp();

        // --- GEMM 2: O = H @ W1b^T + b1b ---
        #pragma unroll
        for (int i = 0; i < 8; ++i) acc[i] = bias_b;

        for (int k4 = 0; k4 < 32; ++k4) {
            float4 w0 = Wb4[(k4 * 4 + 0) * 32 + l];
            float4 w1 = Wb4[(k4 * 4 + 1) * 32 + l];
            float4 w2 = Wb4[(k4 * 4 + 2) * 32 + l];
            float4 w3 = Wb4[(k4 * 4 + 3) * 32 + l];
            #pragma unroll
            for (int i = 0; i < 8; ++i) {
                float4 v = V4[(i0 + i) * 32 + k4];
                acc[i].x = fmaf(v.x, w0.x, acc[i].x);
                acc[i].y = fmaf(v.x, w0.y, acc[i].y);
                acc[i].z = fmaf(v.x, w0.z, acc[i].z);
                acc[i].w = fmaf(v.x, w0.w, acc[i].w);
                acc[i].x = fmaf(v.y, w1.x, acc[i].x);
                acc[i].y = fmaf(v.y, w1.y, acc[i].y);
                acc[i].z = fmaf(v.y, w1.z, acc[i].z);
                acc[i].w = fmaf(v.y, w1.w, acc[i].w);
                acc[i].x = fmaf(v.z, w2.x, acc[i].x);
                acc[i].y = fmaf(v.z, w2.y, acc[i].y);
                acc[i].z = fmaf(v.z, w2.z, acc[i].z);
                acc[i].w = fmaf(v.z, w2.w, acc[i].w);
                acc[i].x = fmaf(v.w, w3.x, acc[i].x);
                acc[i].y = fmaf(v.w, w3.y, acc[i].y);
                acc[i].z = fmaf(v.w, w3.z, acc[i].z);
                acc[i].w = fmaf(v.w, w3.w, acc[i].w);
            }
        }

        // Scatter-sum
        #pragma unroll
        for (int i = 0; i < 8; ++i) {
            int t = s_tgt[i0 + i];
            if (t >= 0) {
                float* dst = g_accum + (size_t)t * 128 + 4 * l;
                atomicAdd(dst + 0, acc[i].x);
                atomicAdd(dst + 1, acc[i].y);
                atomicAdd(dst + 2, acc[i].z);
                atomicAdd(dst + 3, acc[i].w);
            }
        }
    }
}

// ---------------------------------------------------------------------------
// Node kernel: per 32-node tile,
//   IN = [x_g (128), a (128), u[batch_g] (64)]  (320)
//   H = leaky(IN @ W2a^T + b2a);  OUT = H @ W2b^T + b2b
// ---------------------------------------------------------------------------
#define NT   32
#define NTH  256

#define NO_W    0
#define NO_IN   40960
#define NO_B2A  51200
#define NO_B2B  51328
#define NO_IDX  51456
#define N_SMEM_BYTES ((51456 + NT) * 4)

__global__ void __launch_bounds__(NTH, 1)
node_kernel(const float* __restrict__ x_g,
            const float* __restrict__ u,
            const float* __restrict__ W2a, const float* __restrict__ b2a,
            const float* __restrict__ W2b, const float* __restrict__ b2b,
            const int* __restrict__ batch_g,
            float* __restrict__ out, int NG)
{
    extern __shared__ float sm[];
    float* Wt   = sm + NO_W;
    float* IN   = sm + NO_IN;
    float* sb2a = sm + NO_B2A;
    float* sb2b = sm + NO_B2B;
    int*   s_b  = reinterpret_cast<int*>(sm + NO_IDX);

    const int tid = threadIdx.x;
    const int n0 = blockIdx.x * NT;

    for (int t = tid; t < 128 * 320; t += NTH) {
        int j = t / 320, k = t % 320;
        Wt[k * 128 + j] = W2a[t];
    }
    if (tid < 128) { sb2a[tid] = b2a[tid]; sb2b[tid] = b2b[tid]; }
    if (tid < NT) {
        int n = n0 + tid;
        int b = 0;
        if (n < NG) {
            b = batch_g[n];
            if (b < 0) b = 0;
            if (b > 15) b = 15;
        }
        s_b[tid] = b;
    }
    __syncthreads();

    float4* IN4 = reinterpret_cast<float4*>(IN);
    const float4* Wt4 = reinterpret_cast<const float4*>(Wt);

    for (int f = tid; f < NT * 80; f += NTH) {
        int i = f / 80, c = f % 80;
        int n = n0 + i;
        float4 val = make_float4(0.f, 0.f, 0.f, 0.f);
        if (n < NG) {
            if (c < 32)
                val = reinterpret_cast<const float4*>(x_g)[(size_t)n * 32 + c];
            else if (c < 64)
                val = reinterpret_cast<const float4*>(g_accum)[(size_t)n * 32 + (c - 32)];
            else
                val = reinterpret_cast<const float4*>(u)[(size_t)s_b[i] * 16 + (c - 64)];
        }
        IN4[f] = val;
    }
    __syncthreads();

    const int w = tid >> 5;
    const int l = tid & 31;
    const int i0 = w * 4;
    const float4 ba = reinterpret_cast<const float4*>(sb2a)[l];
    const float4 bb = reinterpret_cast<const float4*>(sb2b)[l];

    float4 acc[4];
    #pragma unroll
    for (int i = 0; i < 4; ++i) acc[i] = ba;

    // --- GEMM 1: K = 320 ---
    for (int k4 = 0; k4 < 80; ++k4) {
        float4 w0 = Wt4[(k4 * 4 + 0) * 32 + l];
        float4 w1 = Wt4[(k4 * 4 + 1) * 32 + l];
        float4 w2 = Wt4[(k4 * 4 + 2) * 32 + l];
        float4 w3 = Wt4[(k4 * 4 + 3) * 32 + l];
        #pragma unroll
        for (int i = 0; i < 4; ++i) {
            float4 v = IN4[(i0 + i) * 80 + k4];
            acc[i].x = fmaf(v.x, w0.x, acc[i].x);
            acc[i].y = fmaf(v.x, w0.y, acc[i].y);
            acc[i].z = fmaf(v.x, w0.z, acc[i].z);
            acc[i].w = fmaf(v.x, w0.w, acc[i].w);
            acc[i].x = fmaf(v.y, w1.x, acc[i].x);
            acc[i].y = fmaf(v.y, w1.y, acc[i].y);
            acc[i].z = fmaf(v.y, w1.z, acc[i].z);
            acc[i].w = fmaf(v.y, w1.w, acc[i].w);
            acc[i].x = fmaf(v.z, w2.x, acc[i].x);
            acc[i].y = fmaf(v.z, w2.y, acc[i].y);
            acc[i].z = fmaf(v.z, w2.z, acc[i].z);
            acc[i].w = fmaf(v.z, w2.w, acc[i].w);
            acc[i].x = fmaf(v.w, w3.x, acc[i].x);
            acc[i].y = fmaf(v.w, w3.y, acc[i].y);
            acc[i].z = fmaf(v.w, w3.z, acc[i].z);
            acc[i].w = fmaf(v.w, w3.w, acc[i].w);
        }
    }

    __syncwarp();
    #pragma unroll
    for (int i = 0; i < 4; ++i) {
        float4 h;
        h.x = lrelu(acc[i].x); h.y = lrelu(acc[i].y);
        h.z = lrelu(acc[i].z); h.w = lrelu(acc[i].w);
        IN4[(i0 + i) * 80 + l] = h;
    }
    __syncthreads();

    for (int t = tid; t < 128 * 128; t += NTH) {
        int j = t >> 7, k = t & 127;
        Wt[k * 128 + j] = W2b[t];
    }
    __syncthreads();

    // --- GEMM 2: K = 128 ---
    #pragma unroll
    for (int i = 0; i < 4; ++i) acc[i] = bb;

    for (int k4 = 0; k4 < 32; ++k4) {
        float4 w0 = Wt4[(k4 * 4 + 0) * 32 + l];
        float4 w1 = Wt4[(k4 * 4 + 1) * 32 + l];
        float4 w2 = Wt4[(k4 * 4 + 2) * 32 + l];
        float4 w3 = Wt4[(k4 * 4 + 3) * 32 + l];
        #pragma unroll
        for (int i = 0; i < 4; ++i) {
            float4 v = IN4[(i0 + i) * 80 + k4];
            acc[i].x = fmaf(v.x, w0.x, acc[i].x);
            acc[i].y = fmaf(v.x, w0.y, acc[i].y);
            acc[i].z = fmaf(v.x, w0.z, acc[i].z);
            acc[i].w = fmaf(v.x, w0.w, acc[i].w);
            acc[i].x = fmaf(v.y, w1.x, acc[i].x);
            acc[i].y = fmaf(v.y, w1.y, acc[i].y);
            acc[i].z = fmaf(v.y, w1.z, acc[i].z);
            acc[i].w = fmaf(v.y, w1.w, acc[i].w);
            acc[i].x = fmaf(v.z, w2.x, acc[i].x);
            acc[i].y = fmaf(v.z, w2.y, acc[i].y);
            acc[i].z = fmaf(v.z, w2.z, acc[i].z);
            acc[i].w = fmaf(v.z, w2.w, acc[i].w);
            acc[i].x = fmaf(v.w, w3.x, acc[i].x);
            acc[i].y = fmaf(v.w, w3.y, acc[i].y);
            acc[i].z = fmaf(v.w, w3.z, acc[i].z);
            acc[i].w = fmaf(v.w, w3.w, acc[i].w);
        }
    }

    #pragma unroll
    for (int i = 0; i < 4; ++i) {
        int n = n0 + i0 + i;
        if (n < NG)
            reinterpret_cast<float4*>(out)[(size_t)n * 32 + l] = acc[i];
    }
}

// ---------------------------------------------------------------------------
// kernel_launch
// Inputs (metadata order; edge_index / batch_g are int32 — JAX default x64-off
// silently downcasts the reference's .astype(jnp.int64)):
//  0 x_h [50000,64] f32      1 x_g [50000,128] f32   2 edge_attr [1.6M,64] f32
//  3 u [16,64] f32           4 W1a [128,128]         5 b1a [128]
//  6 W1b [128,128]           7 b1b [128]             8 W2a [128,320]
//  9 b2a [128]              10 W2b [128,128]        11 b2b [128]
// 12 edge_index [2,1.6M] i32                        13 batch_g [50000] i32
// ---------------------------------------------------------------------------
extern "C" void kernel_launch(void* const* d_in, const int* in_sizes, int n_in,
                              void* d_out, int out_size) {
    const float* x_h       = (const float*)d_in[0];
    const float* x_g       = (const float*)d_in[1];
    const float* edge_attr = (const float*)d_in[2];
    const float* u         = (const float*)d_in[3];
    const float* W1a       = (const float*)d_in[4];
    const float* b1a       = (const float*)d_in[5];
    const float* W1b       = (const float*)d_in[6];
    const float* b1b       = (const float*)d_in[7];
    const float* W2a       = (const float*)d_in[8];
    const float* b2a       = (const float*)d_in[9];
    const float* W2b       = (const float*)d_in[10];
    const float* b2b       = (const float*)d_in[11];
    const int* eidx        = (const int*)d_in[12];
    const int* batch       = (const int*)d_in[13];
    float* out = (float*)d_out;

    const int E  = in_sizes[12] / 2;
    const int NG = in_sizes[1] / N_GC;

    cudaFuncSetAttribute(edge_kernel, cudaFuncAttributeMaxDynamicSharedMemorySize,
                         E_SMEM_BYTES);
    cudaFuncSetAttribute(node_kernel, cudaFuncAttributeMaxDynamicSharedMemorySize,
                         N_SMEM_BYTES);

    zero_accum_kernel<<<1024, 256>>>();
    edge_kernel<<<152, ETH, E_SMEM_BYTES>>>(x_h, edge_attr, W1a, b1a, W1b, b1b,
                                            eidx, E);
    int node_blocks = (NG + NT - 1) / NT;
    node_kernel<<<node_blocks, NTH, N_SMEM_BYTES>>>(x_g, u, W2a, b2a, W2b, b2b,
                                                    batch, out, NG);
}

// round 8
// speedup vs baseline: 1.6604x; 1.6604x over previous
#include <cuda_runtime.h>
#include <cuda_bf16.h>
#include <cstdint>

#define N_H_NODES 50000
#define N_G_NODES 50000
#define N_GC 128

// Scatter-sum accumulator: 25.6 MB static scratch, 128B aligned (float4 access).
__device__ __align__(128) float g_accum[(size_t)N_G_NODES * N_GC];

__device__ __forceinline__ float lrelu(float v) { return v >= 0.0f ? v : 0.1f * v; }

// ---------------------------------------------------------------------------
// mma.sync / ldmatrix helpers (baseline PTX, compiles for compute_103)
// ---------------------------------------------------------------------------
__device__ __forceinline__ uint32_t smem_to_u32(const void* p) {
    uint32_t a;
    asm("{ .reg .u64 t; cvta.to.shared.u64 t, %1; cvt.u32.u64 %0, t; }" : "=r"(a) : "l"(p));
    return a;
}

__device__ __forceinline__ void ldsm4(uint32_t a[4], uint32_t addr) {
    asm volatile("ldmatrix.sync.aligned.m8n8.x4.shared.b16 {%0,%1,%2,%3}, [%4];"
                 : "=r"(a[0]), "=r"(a[1]), "=r"(a[2]), "=r"(a[3]) : "r"(addr));
}
__device__ __forceinline__ void ldsm2t(uint32_t b[2], uint32_t addr) {
    asm volatile("ldmatrix.sync.aligned.m8n8.x2.trans.shared.b16 {%0,%1}, [%2];"
                 : "=r"(b[0]), "=r"(b[1]) : "r"(addr));
}
__device__ __forceinline__ void mma16816(float d[4], const uint32_t a[4], const uint32_t b[2]) {
    asm volatile("mma.sync.aligned.m16n8k16.row.col.f32.bf16.bf16.f32 "
                 "{%0,%1,%2,%3}, {%4,%5,%6,%7}, {%8,%9}, {%0,%1,%2,%3};"
                 : "+f"(d[0]), "+f"(d[1]), "+f"(d[2]), "+f"(d[3])
                 : "r"(a[0]), "r"(a[1]), "r"(a[2]), "r"(a[3]), "r"(b[0]), "r"(b[1]));
}

__device__ __forceinline__ void bf16_split(float v, uint16_t& h, uint16_t& l) {
    __nv_bfloat16 hb = __float2bfloat16_rn(v);
    h = __bfloat16_as_ushort(hb);
    l = __bfloat16_as_ushort(__float2bfloat16_rn(v - __bfloat162float(hb)));
}

__device__ __forceinline__ void red_add_v2(float* p, float a, float b) {
    asm volatile("red.global.add.v2.f32 [%0], {%1, %2};" :: "l"(p), "f"(a), "f"(b) : "memory");
}

// ---------------------------------------------------------------------------
// zero accumulator
// ---------------------------------------------------------------------------
__global__ void zero_accum_kernel() {
    size_t n4 = (size_t)N_G_NODES * N_GC / 4;
    float4 z = make_float4(0.f, 0.f, 0.f, 0.f);
    float4* p = reinterpret_cast<float4*>(g_accum);
    for (size_t i = (size_t)blockIdx.x * blockDim.x + threadIdx.x; i < n4;
         i += (size_t)gridDim.x * blockDim.x)
        p[i] = z;
}

// ---------------------------------------------------------------------------
// Fused edge MLP kernel (persistent), bf16x3 tensor-core path.
//
// Per 128-edge tile:
//   V[r] = [x_h[src[r]] (64) | edge_attr[r] (64)]  split into bf16 hi/lo planes
//   GEMM1: H = lrelu(V @ Wa^T + b1a)   (mma.sync, 3-term bf16 split)
//   H split back into the V planes
//   GEMM2: O = H @ Wb^T + b1b
//   red.global.add.v2 O rows into g_accum[tgt[r]]
//
// SMEM planes store weights TRANSPOSED: Wt[k][n] (k rows, n = output col),
// padded row stride PADK=136 bf16 (272B) -> conflict-free ldmatrix.
// 8 warps; warp tile m64 x n32 (warp = (mg<<2)|ng, mg in {0,1}, ng in 0..3).
// ---------------------------------------------------------------------------
#define ETH   256
#define PADK  136
#define PLANE (128 * PADK * 2)     // 34816 bytes per bf16 plane

#define SO_WAHI 0
#define SO_WALO (SO_WAHI + PLANE)
#define SO_WBHI (SO_WALO + PLANE)
#define SO_WBLO (SO_WBHI + PLANE)
#define SO_VHI  (SO_WBLO + PLANE)
#define SO_VLO  (SO_VHI + PLANE)
#define SO_B1A  (SO_VLO + PLANE)          // float[128]
#define SO_B1B  (SO_B1A + 512)
#define SO_SRC  (SO_B1B + 512)            // int[128]
#define SO_TGT  (SO_SRC + 512)
#define E_SMEM_BYTES (SO_TGT + 512)       // 210944

// 3-term bf16 GEMM: acc[4][4][4] += A(V planes) @ B(W planes), one k-sweep.
__device__ __forceinline__ void gemm_tile(float acc[4][4][4],
                                          uint32_t vhi, uint32_t vlo,
                                          uint32_t whi, uint32_t wlo,
                                          int m0, int n0, uint32_t aoff, uint32_t boff)
{
    #pragma unroll
    for (int ks = 0; ks < 8; ++ks) {
        uint32_t bhi[4][2], blo[4][2];
        #pragma unroll
        for (int nj = 0; nj < 4; ++nj) {
            uint32_t bb = (uint32_t)((ks * 16) * PADK + n0 + 8 * nj) * 2 + boff;
            ldsm2t(bhi[nj], whi + bb);
            ldsm2t(blo[nj], wlo + bb);
        }
        #pragma unroll
        for (int mi = 0; mi < 4; ++mi) {
            uint32_t ab = (uint32_t)((m0 + 16 * mi) * PADK + ks * 16) * 2 + aoff;
            uint32_t ahi[4], alo[4];
            ldsm4(ahi, vhi + ab);
            ldsm4(alo, vlo + ab);
            #pragma unroll
            for (int nj = 0; nj < 4; ++nj) {
                mma16816(acc[mi][nj], ahi, bhi[nj]);
                mma16816(acc[mi][nj], alo, bhi[nj]);
                mma16816(acc[mi][nj], ahi, blo[nj]);
            }
        }
    }
}

__global__ void __launch_bounds__(ETH, 1)
edge_kernel(const float* __restrict__ x_h,
            const float* __restrict__ edge_attr,
            const float* __restrict__ W1a, const float* __restrict__ b1a,
            const float* __restrict__ W1b, const float* __restrict__ b1b,
            const int* __restrict__ eidx, int E)
{
    extern __shared__ char smc[];
    const uint32_t sb = smem_to_u32(smc);
    uint16_t* WaHi = reinterpret_cast<uint16_t*>(smc + SO_WAHI);
    uint16_t* WaLo = reinterpret_cast<uint16_t*>(smc + SO_WALO);
    uint16_t* WbHi = reinterpret_cast<uint16_t*>(smc + SO_WBHI);
    uint16_t* WbLo = reinterpret_cast<uint16_t*>(smc + SO_WBLO);
    uint32_t* Vhi32 = reinterpret_cast<uint32_t*>(smc + SO_VHI);
    uint32_t* Vlo32 = reinterpret_cast<uint32_t*>(smc + SO_VLO);
    float* sb1a = reinterpret_cast<float*>(smc + SO_B1A);
    float* sb1b = reinterpret_cast<float*>(smc + SO_B1B);
    int*   s_src = reinterpret_cast<int*>(smc + SO_SRC);
    int*   s_tgt = reinterpret_cast<int*>(smc + SO_TGT);

    const int tid  = threadIdx.x;
    const int wid  = tid >> 5;
    const int lane = tid & 31;

    // Weights: store TRANSPOSED + split: Wt[k][n] = W[n][k]
    for (int t = tid; t < 128 * 128; t += ETH) {
        int n = t >> 7, k = t & 127;
        uint16_t h, l;
        bf16_split(W1a[t], h, l);
        WaHi[k * PADK + n] = h; WaLo[k * PADK + n] = l;
        bf16_split(W1b[t], h, l);
        WbHi[k * PADK + n] = h; WbLo[k * PADK + n] = l;
    }
    if (tid < 128) { sb1a[tid] = b1a[tid]; sb1b[tid] = b1b[tid]; }

    const int mg = wid >> 2;           // 0..1
    const int ng = wid & 3;            // 0..3
    const int m0 = mg * 64;
    const int n0 = ng * 32;
    const int qr = lane >> 2;          // fragment row within m8
    const int qc = 2 * (lane & 3);     // fragment col pair base

    // ldmatrix per-lane byte offsets
    const uint32_t aoff = (uint32_t)(lane & 15) * (PADK * 2) + (uint32_t)(lane >> 4) * 16;
    const uint32_t boff = (uint32_t)(lane & 15) * (PADK * 2);

    const uint32_t vhiA = sb + SO_VHI, vloA = sb + SO_VLO;
    const uint32_t wahiA = sb + SO_WAHI, waloA = sb + SO_WALO;
    const uint32_t wbhiA = sb + SO_WBHI, wbloA = sb + SO_WBLO;

    const int* srcp = eidx;
    const int* tgtp = eidx + E;
    const int numTiles = (E + 127) >> 7;

    for (int tile = blockIdx.x; tile < numTiles; tile += gridDim.x) {
        const int e0 = tile * 128;
        __syncthreads();   // previous tile fully consumed / weights staged

        if (tid < 128) {
            int e = e0 + tid;
            int s = 0, t = -1;
            if (e < E) {
                s = srcp[e];
                t = tgtp[e];
                if (s < 0) s = 0;
                if (s >= N_H_NODES) s = N_H_NODES - 1;
                if (t < 0 || t >= N_G_NODES) t = -1;
            }
            s_src[tid] = s;
            s_tgt[tid] = t;
        }
        __syncthreads();

        // Gather + split into V planes. 2 threads per row, 64 cols each.
        {
            const int r = tid >> 1;
            const int half = tid & 1;
            const int ge = e0 + r;
            const int gec = ge < E ? ge : E - 1;
            const float4* rp = (half == 0)
                ? reinterpret_cast<const float4*>(x_h + (size_t)s_src[r] * 64)
                : reinterpret_cast<const float4*>(edge_attr + (size_t)gec * 64);
            const int base = (r * PADK + half * 64) >> 1;   // u32 index
            #pragma unroll
            for (int q = 0; q < 16; ++q) {
                float4 v = rp[q];
                uint16_t h0, l0, h1, l1;
                bf16_split(v.x, h0, l0); bf16_split(v.y, h1, l1);
                Vhi32[base + 2 * q]     = (uint32_t)h0 | ((uint32_t)h1 << 16);
                Vlo32[base + 2 * q]     = (uint32_t)l0 | ((uint32_t)l1 << 16);
                bf16_split(v.z, h0, l0); bf16_split(v.w, h1, l1);
                Vhi32[base + 2 * q + 1] = (uint32_t)h0 | ((uint32_t)h1 << 16);
                Vlo32[base + 2 * q + 1] = (uint32_t)l0 | ((uint32_t)l1 << 16);
            }
        }
        __syncthreads();

        // --- GEMM 1 ---
        float acc[4][4][4];
        #pragma unroll
        for (int mi = 0; mi < 4; ++mi)
            #pragma unroll
            for (int nj = 0; nj < 4; ++nj)
                #pragma unroll
                for (int q = 0; q < 4; ++q) acc[mi][nj][q] = 0.f;

        gemm_tile(acc, vhiA, vloA, wahiA, waloA, m0, n0, aoff, boff);
        __syncthreads();   // all reads of V done before overwrite

        // H = lrelu(acc + b1a) -> split back into V planes
        #pragma unroll
        for (int mi = 0; mi < 4; ++mi) {
            const int r1 = m0 + 16 * mi + qr;
            #pragma unroll
            for (int nj = 0; nj < 4; ++nj) {
                const int c = n0 + 8 * nj + qc;
                const float bx = sb1a[c], by = sb1a[c + 1];
                uint16_t h0, l0, h1, l1;
                float v0 = lrelu(acc[mi][nj][0] + bx);
                float v1 = lrelu(acc[mi][nj][1] + by);
                bf16_split(v0, h0, l0); bf16_split(v1, h1, l1);
                Vhi32[(r1 * PADK + c) >> 1] = (uint32_t)h0 | ((uint32_t)h1 << 16);
                Vlo32[(r1 * PADK + c) >> 1] = (uint32_t)l0 | ((uint32_t)l1 << 16);
                v0 = lrelu(acc[mi][nj][2] + bx);
                v1 = lrelu(acc[mi][nj][3] + by);
                bf16_split(v0, h0, l0); bf16_split(v1, h1, l1);
                Vhi32[((r1 + 8) * PADK + c) >> 1] = (uint32_t)h0 | ((uint32_t)h1 << 16);
                Vlo32[((r1 + 8) * PADK + c) >> 1] = (uint32_t)l0 | ((uint32_t)l1 << 16);
            }
        }
        __syncthreads();

        // --- GEMM 2 ---
        #pragma unroll
        for (int mi = 0; mi < 4; ++mi)
            #pragma unroll
            for (int nj = 0; nj < 4; ++nj)
                #pragma unroll
                for (int q = 0; q < 4; ++q) acc[mi][nj][q] = 0.f;

        gemm_tile(acc, vhiA, vloA, wbhiA, wbloA, m0, n0, aoff, boff);

        // Scatter: O = acc + b1b -> red.add.v2 into g_accum[tgt]
        #pragma unroll
        for (int mi = 0; mi < 4; ++mi) {
            const int r1 = m0 + 16 * mi + qr;
            const int t0 = s_tgt[r1];
            const int t1 = s_tgt[r1 + 8];
            #pragma unroll
            for (int nj = 0; nj < 4; ++nj) {
                const int c = n0 + 8 * nj + qc;
                const float bx = sb1b[c], by = sb1b[c + 1];
                if (t0 >= 0)
                    red_add_v2(g_accum + (size_t)t0 * 128 + c,
                               acc[mi][nj][0] + bx, acc[mi][nj][1] + by);
                if (t1 >= 0)
                    red_add_v2(g_accum + (size_t)t1 * 128 + c,
                               acc[mi][nj][2] + bx, acc[mi][nj][3] + by);
            }
        }
    }
}

// ---------------------------------------------------------------------------
// Node kernel (unchanged from passing R5 version)
// ---------------------------------------------------------------------------
#define NT   32
#define NTH  256
#define NO_W    0
#define NO_IN   40960
#define NO_B2A  51200
#define NO_B2B  51328
#define NO_IDX  51456
#define N_SMEM_BYTES ((51456 + NT) * 4)

__global__ void __launch_bounds__(NTH, 1)
node_kernel(const float* __restrict__ x_g,
            const float* __restrict__ u,
            const float* __restrict__ W2a, const float* __restrict__ b2a,
            const float* __restrict__ W2b, const float* __restrict__ b2b,
            const int* __restrict__ batch_g,
            float* __restrict__ out, int NG)
{
    extern __shared__ float sm[];
    float* Wt   = sm + NO_W;
    float* IN   = sm + NO_IN;
    float* sb2a = sm + NO_B2A;
    float* sb2b = sm + NO_B2B;
    int*   s_b  = reinterpret_cast<int*>(sm + NO_IDX);

    const int tid = threadIdx.x;
    const int n0 = blockIdx.x * NT;

    for (int t = tid; t < 128 * 320; t += NTH) {
        int j = t / 320, k = t % 320;
        Wt[k * 128 + j] = W2a[t];
    }
    if (tid < 128) { sb2a[tid] = b2a[tid]; sb2b[tid] = b2b[tid]; }
    if (tid < NT) {
        int n = n0 + tid;
        int b = 0;
        if (n < NG) {
            b = batch_g[n];
            if (b < 0) b = 0;
            if (b > 15) b = 15;
        }
        s_b[tid] = b;
    }
    __syncthreads();

    float4* IN4 = reinterpret_cast<float4*>(IN);
    const float4* Wt4 = reinterpret_cast<const float4*>(Wt);

    for (int f = tid; f < NT * 80; f += NTH) {
        int i = f / 80, c = f % 80;
        int n = n0 + i;
        float4 val = make_float4(0.f, 0.f, 0.f, 0.f);
        if (n < NG) {
            if (c < 32)
                val = reinterpret_cast<const float4*>(x_g)[(size_t)n * 32 + c];
            else if (c < 64)
                val = reinterpret_cast<const float4*>(g_accum)[(size_t)n * 32 + (c - 32)];
            else
                val = reinterpret_cast<const float4*>(u)[(size_t)s_b[i] * 16 + (c - 64)];
        }
        IN4[f] = val;
    }
    __syncthreads();

    const int w = tid >> 5;
    const int l = tid & 31;
    const int i0 = w * 4;
    const float4 ba = reinterpret_cast<const float4*>(sb2a)[l];
    const float4 bb = reinterpret_cast<const float4*>(sb2b)[l];

    float4 acc[4];
    #pragma unroll
    for (int i = 0; i < 4; ++i) acc[i] = ba;

    for (int k4 = 0; k4 < 80; ++k4) {
        float4 w0 = Wt4[(k4 * 4 + 0) * 32 + l];
        float4 w1 = Wt4[(k4 * 4 + 1) * 32 + l];
        float4 w2 = Wt4[(k4 * 4 + 2) * 32 + l];
        float4 w3 = Wt4[(k4 * 4 + 3) * 32 + l];
        #pragma unroll
        for (int i = 0; i < 4; ++i) {
            float4 v = IN4[(i0 + i) * 80 + k4];
            acc[i].x = fmaf(v.x, w0.x, acc[i].x); acc[i].y = fmaf(v.x, w0.y, acc[i].y);
            acc[i].z = fmaf(v.x, w0.z, acc[i].z); acc[i].w = fmaf(v.x, w0.w, acc[i].w);
            acc[i].x = fmaf(v.y, w1.x, acc[i].x); acc[i].y = fmaf(v.y, w1.y, acc[i].y);
            acc[i].z = fmaf(v.y, w1.z, acc[i].z); acc[i].w = fmaf(v.y, w1.w, acc[i].w);
            acc[i].x = fmaf(v.z, w2.x, acc[i].x); acc[i].y = fmaf(v.z, w2.y, acc[i].y);
            acc[i].z = fmaf(v.z, w2.z, acc[i].z); acc[i].w = fmaf(v.z, w2.w, acc[i].w);
            acc[i].x = fmaf(v.w, w3.x, acc[i].x); acc[i].y = fmaf(v.w, w3.y, acc[i].y);
            acc[i].z = fmaf(v.w, w3.z, acc[i].z); acc[i].w = fmaf(v.w, w3.w, acc[i].w);
        }
    }

    __syncwarp();
    #pragma unroll
    for (int i = 0; i < 4; ++i) {
        float4 h;
        h.x = lrelu(acc[i].x); h.y = lrelu(acc[i].y);
        h.z = lrelu(acc[i].z); h.w = lrelu(acc[i].w);
        IN4[(i0 + i) * 80 + l] = h;
    }
    __syncthreads();

    for (int t = tid; t < 128 * 128; t += NTH) {
        int j = t >> 7, k = t & 127;
        Wt[k * 128 + j] = W2b[t];
    }
    __syncthreads();

    #pragma unroll
    for (int i = 0; i < 4; ++i) acc[i] = bb;

    for (int k4 = 0; k4 < 32; ++k4) {
        float4 w0 = Wt4[(k4 * 4 + 0) * 32 + l];
        float4 w1 = Wt4[(k4 * 4 + 1) * 32 + l];
        float4 w2 = Wt4[(k4 * 4 + 2) * 32 + l];
        float4 w3 = Wt4[(k4 * 4 + 3) * 32 + l];
        #pragma unroll
        for (int i = 0; i < 4; ++i) {
            float4 v = IN4[(i0 + i) * 80 + k4];
            acc[i].x = fmaf(v.x, w0.x, acc[i].x); acc[i].y = fmaf(v.x, w0.y, acc[i].y);
            acc[i].z = fmaf(v.x, w0.z, acc[i].z); acc[i].w = fmaf(v.x, w0.w, acc[i].w);
            acc[i].x = fmaf(v.y, w1.x, acc[i].x); acc[i].y = fmaf(v.y, w1.y, acc[i].y);
            acc[i].z = fmaf(v.y, w1.z, acc[i].z); acc[i].w = fmaf(v.y, w1.w, acc[i].w);
            acc[i].x = fmaf(v.z, w2.x, acc[i].x); acc[i].y = fmaf(v.z, w2.y, acc[i].y);
            acc[i].z = fmaf(v.z, w2.z, acc[i].z); acc[i].w = fmaf(v.z, w2.w, acc[i].w);
            acc[i].x = fmaf(v.w, w3.x, acc[i].x); acc[i].y = fmaf(v.w, w3.y, acc[i].y);
            acc[i].z = fmaf(v.w, w3.z, acc[i].z); acc[i].w = fmaf(v.w, w3.w, acc[i].w);
        }
    }

    #pragma unroll
    for (int i = 0; i < 4; ++i) {
        int n = n0 + i0 + i;
        if (n < NG)
            reinterpret_cast<float4*>(out)[(size_t)n * 32 + l] = acc[i];
    }
}

// ---------------------------------------------------------------------------
// kernel_launch
// Inputs: 0 x_h, 1 x_g, 2 edge_attr, 3 u, 4 W1a, 5 b1a, 6 W1b, 7 b1b,
//         8 W2a, 9 b2a, 10 W2b, 11 b2b, 12 edge_index (int32), 13 batch_g (int32)
// ---------------------------------------------------------------------------
extern "C" void kernel_launch(void* const* d_in, const int* in_sizes, int n_in,
                              void* d_out, int out_size) {
    const float* x_h       = (const float*)d_in[0];
    const float* x_g       = (const float*)d_in[1];
    const float* edge_attr = (const float*)d_in[2];
    const float* u         = (const float*)d_in[3];
    const float* W1a       = (const float*)d_in[4];
    const float* b1a       = (const float*)d_in[5];
    const float* W1b       = (const float*)d_in[6];
    const float* b1b       = (const float*)d_in[7];
    const float* W2a       = (const float*)d_in[8];
    const float* b2a       = (const float*)d_in[9];
    const float* W2b       = (const float*)d_in[10];
    const float* b2b       = (const float*)d_in[11];
    const int* eidx        = (const int*)d_in[12];
    const int* batch       = (const int*)d_in[13];
    float* out = (float*)d_out;

    const int E  = in_sizes[12] / 2;
    const int NG = in_sizes[1] / N_GC;

    cudaFuncSetAttribute(edge_kernel, cudaFuncAttributeMaxDynamicSharedMemorySize,
                         E_SMEM_BYTES);
    cudaFuncSetAttribute(node_kernel, cudaFuncAttributeMaxDynamicSharedMemorySize,
                         N_SMEM_BYTES);

    zero_accum_kernel<<<1024, 256>>>();
    edge_kernel<<<152, ETH, E_SMEM_BYTES>>>(x_h, edge_attr, W1a, b1a, W1b, b1b,
                                            eidx, E);
    int node_blocks = (NG + NT - 1) / NT;
    node_kernel<<<node_blocks, NTH, N_SMEM_BYTES>>>(x_g, u, W2a, b2a, W2b, b2b,
                                                    batch, out, NG);
}

// round 9
// speedup vs baseline: 1.6704x; 1.0060x over previous
#include <cuda_runtime.h>
#include <cuda_bf16.h>
#include <cstdint>

#define N_H_NODES 50000
#define N_G_NODES 50000
#define N_GC 128

// Scatter-sum accumulator: 25.6 MB static scratch, 128B aligned (float4 access).
__device__ __align__(128) float g_accum[(size_t)N_G_NODES * N_GC];

__device__ __forceinline__ float lrelu(float v) { return v >= 0.0f ? v : 0.1f * v; }

// ---------------------------------------------------------------------------
// mma.sync / ldmatrix helpers (baseline PTX, compiles for compute_103)
// ---------------------------------------------------------------------------
__device__ __forceinline__ uint32_t smem_to_u32(const void* p) {
    uint32_t a;
    asm("{ .reg .u64 t; cvta.to.shared.u64 t, %1; cvt.u32.u64 %0, t; }" : "=r"(a) : "l"(p));
    return a;
}

__device__ __forceinline__ void ldsm4(uint32_t a[4], uint32_t addr) {
    asm volatile("ldmatrix.sync.aligned.m8n8.x4.shared.b16 {%0,%1,%2,%3}, [%4];"
                 : "=r"(a[0]), "=r"(a[1]), "=r"(a[2]), "=r"(a[3]) : "r"(addr));
}
__device__ __forceinline__ void ldsm4t(uint32_t b[4], uint32_t addr) {
    asm volatile("ldmatrix.sync.aligned.m8n8.x4.trans.shared.b16 {%0,%1,%2,%3}, [%4];"
                 : "=r"(b[0]), "=r"(b[1]), "=r"(b[2]), "=r"(b[3]) : "r"(addr));
}
__device__ __forceinline__ void mma16816(float d[4], const uint32_t a[4], const uint32_t b[2]) {
    asm volatile("mma.sync.aligned.m16n8k16.row.col.f32.bf16.bf16.f32 "
                 "{%0,%1,%2,%3}, {%4,%5,%6,%7}, {%8,%9}, {%0,%1,%2,%3};"
                 : "+f"(d[0]), "+f"(d[1]), "+f"(d[2]), "+f"(d[3])
                 : "r"(a[0]), "r"(a[1]), "r"(a[2]), "r"(a[3]), "r"(b[0]), "r"(b[1]));
}

__device__ __forceinline__ void bf16_split(float v, uint16_t& h, uint16_t& l) {
    __nv_bfloat16 hb = __float2bfloat16_rn(v);
    h = __bfloat16_as_ushort(hb);
    l = __bfloat16_as_ushort(__float2bfloat16_rn(v - __bfloat162float(hb)));
}

__device__ __forceinline__ void red_add_v4(float* p, float a, float b, float c, float d) {
    asm volatile("red.global.add.v4.f32 [%0], {%1, %2, %3, %4};"
                 :: "l"(p), "f"(a), "f"(b), "f"(c), "f"(d) : "memory");
}

// ---------------------------------------------------------------------------
// zero accumulator
// ---------------------------------------------------------------------------
__global__ void zero_accum_kernel() {
    size_t n4 = (size_t)N_G_NODES * N_GC / 4;
    float4 z = make_float4(0.f, 0.f, 0.f, 0.f);
    float4* p = reinterpret_cast<float4*>(g_accum);
    for (size_t i = (size_t)blockIdx.x * blockDim.x + threadIdx.x; i < n4;
         i += (size_t)gridDim.x * blockDim.x)
        p[i] = z;
}

// ---------------------------------------------------------------------------
// Fused edge MLP (persistent), bf16x3 tensor-core path, warp tile m16 x n128.
//
// Per 128-edge tile:
//   V[r] = [x_h[src[r]] | edge_attr[r]]  -> bf16 hi/lo planes (SMEM)
//   GEMM1: acc = V @ Wa^T (3-term).  Epilogue IN REGISTERS: lrelu(acc+b1a)
//     repacked as GEMM2 A-fragments (C m16n8 layout == A m16k16 layout halves).
//   GEMM2: acc = H @ Wb^T (3-term), A from registers, B from SMEM.
//   O staged to SMEM (V planes are dead after GEMM1) then scattered with
//   red.global.add.v4.f32, row-contiguous.
// ---------------------------------------------------------------------------
#define ETH   256
#define PADK  136
#define PLANE (128 * PADK * 2)     // 34816 bytes per bf16 plane
#define OPAD  132                  // O staging row stride (floats)

#define SO_WAHI 0
#define SO_WALO (SO_WAHI + PLANE)
#define SO_WBHI (SO_WALO + PLANE)
#define SO_WBLO (SO_WBHI + PLANE)
#define SO_VHI  (SO_WBLO + PLANE)          // reused as O staging (128*132*4 = 67584 <= 2*PLANE)
#define SO_VLO  (SO_VHI + PLANE)
#define SO_B1A  (SO_VLO + PLANE)           // float[128]
#define SO_B1B  (SO_B1A + 512)
#define SO_SRC  (SO_B1B + 512)             // int[128]
#define SO_TGT  (SO_SRC + 512)
#define E_SMEM_BYTES (SO_TGT + 512)        // 210944

__global__ void __launch_bounds__(ETH, 1)
edge_kernel(const float* __restrict__ x_h,
            const float* __restrict__ edge_attr,
            const float* __restrict__ W1a, const float* __restrict__ b1a,
            const float* __restrict__ W1b, const float* __restrict__ b1b,
            const int* __restrict__ eidx, int E)
{
    extern __shared__ char smc[];
    const uint32_t sb = smem_to_u32(smc);
    uint16_t* WaHi = reinterpret_cast<uint16_t*>(smc + SO_WAHI);
    uint16_t* WaLo = reinterpret_cast<uint16_t*>(smc + SO_WALO);
    uint16_t* WbHi = reinterpret_cast<uint16_t*>(smc + SO_WBHI);
    uint16_t* WbLo = reinterpret_cast<uint16_t*>(smc + SO_WBLO);
    uint32_t* Vhi32 = reinterpret_cast<uint32_t*>(smc + SO_VHI);
    uint32_t* Vlo32 = reinterpret_cast<uint32_t*>(smc + SO_VLO);
    float* Ost  = reinterpret_cast<float*>(smc + SO_VHI);   // O staging (V dead after GEMM1)
    float* sb1a = reinterpret_cast<float*>(smc + SO_B1A);
    float* sb1b = reinterpret_cast<float*>(smc + SO_B1B);
    int*   s_src = reinterpret_cast<int*>(smc + SO_SRC);
    int*   s_tgt = reinterpret_cast<int*>(smc + SO_TGT);

    const int tid  = threadIdx.x;
    const int wid  = tid >> 5;
    const int lane = tid & 31;

    // Weights: store TRANSPOSED + split: Wt[k][n] = W[n][k]
    for (int t = tid; t < 128 * 128; t += ETH) {
        int n = t >> 7, k = t & 127;
        uint16_t h, l;
        bf16_split(W1a[t], h, l);
        WaHi[k * PADK + n] = h; WaLo[k * PADK + n] = l;
        bf16_split(W1b[t], h, l);
        WbHi[k * PADK + n] = h; WbLo[k * PADK + n] = l;
    }
    if (tid < 128) { sb1a[tid] = b1a[tid]; sb1b[tid] = b1b[tid]; }

    const int m0 = wid * 16;           // warp's 16 rows
    const int qr = lane >> 2;          // fragment row within m8
    const int qt = lane & 3;           // fragment col-pair selector

    // ldmatrix per-lane byte offsets
    //  A x4 (non-trans): lanes 0-15 -> rows 0-15 @k-lo half, 16-31 -> rows @ +16B (k-hi)
    const uint32_t aoff = (uint32_t)(lane & 15) * (PADK * 2) + (uint32_t)(lane >> 4) * 16;
    //  B x4.trans: lanes 0-15 -> k rows 0-15 at n, lanes 16-31 -> same k at n+8
    const uint32_t boff = ((uint32_t)(lane & 15) * PADK + (uint32_t)(lane >> 4) * 8) * 2;

    const uint32_t vhiA = sb + SO_VHI, vloA = sb + SO_VLO;
    const uint32_t wahiA = sb + SO_WAHI, waloA = sb + SO_WALO;
    const uint32_t wbhiA = sb + SO_WBHI, wbloA = sb + SO_WBLO;

    const int* srcp = eidx;
    const int* tgtp = eidx + E;
    const int numTiles = (E + 127) >> 7;

    for (int tile = blockIdx.x; tile < numTiles; tile += gridDim.x) {
        const int e0 = tile * 128;
        __syncthreads();   // previous tile's scatter reads done / weights staged

        if (tid < 128) {
            int e = e0 + tid;
            int s = 0, t = -1;
            if (e < E) {
                s = srcp[e];
                t = tgtp[e];
                if (s < 0) s = 0;
                if (s >= N_H_NODES) s = N_H_NODES - 1;
                if (t < 0 || t >= N_G_NODES) t = -1;
            }
            s_src[tid] = s;
            s_tgt[tid] = t;
        }
        __syncthreads();

        // Gather + split into V planes. 2 threads per row, 64 cols each.
        {
            const int r = tid >> 1;
            const int half = tid & 1;
            const int ge = e0 + r;
            const int gec = ge < E ? ge : E - 1;
            const float4* rp = (half == 0)
                ? reinterpret_cast<const float4*>(x_h + (size_t)s_src[r] * 64)
                : reinterpret_cast<const float4*>(edge_attr + (size_t)gec * 64);
            const int base = (r * PADK + half * 64) >> 1;   // u32 index
            #pragma unroll
            for (int q = 0; q < 16; ++q) {
                float4 v = rp[q];
                uint16_t h0, l0, h1, l1;
                bf16_split(v.x, h0, l0); bf16_split(v.y, h1, l1);
                Vhi32[base + 2 * q]     = (uint32_t)h0 | ((uint32_t)h1 << 16);
                Vlo32[base + 2 * q]     = (uint32_t)l0 | ((uint32_t)l1 << 16);
                bf16_split(v.z, h0, l0); bf16_split(v.w, h1, l1);
                Vhi32[base + 2 * q + 1] = (uint32_t)h0 | ((uint32_t)h1 << 16);
                Vlo32[base + 2 * q + 1] = (uint32_t)l0 | ((uint32_t)l1 << 16);
            }
        }
        __syncthreads();

        // --- GEMM 1: acc[16 n-tiles][4] over full n=128 ---
        float acc[16][4];
        #pragma unroll
        for (int j = 0; j < 16; ++j)
            #pragma unroll
            for (int q = 0; q < 4; ++q) acc[j][q] = 0.f;

        #pragma unroll
        for (int ks = 0; ks < 8; ++ks) {
            uint32_t ahi[4], alo[4];
            const uint32_t ab = (uint32_t)(m0 * PADK + ks * 16) * 2 + aoff;
            ldsm4(ahi, vhiA + ab);
            ldsm4(alo, vloA + ab);
            #pragma unroll
            for (int np = 0; np < 8; ++np) {
                uint32_t bh[4], bl[4];
                const uint32_t bb = (uint32_t)(ks * 16 * PADK + np * 16) * 2 + boff;
                ldsm4t(bh, wahiA + bb);
                ldsm4t(bl, waloA + bb);
                mma16816(acc[2 * np + 0], ahi, bh + 0);
                mma16816(acc[2 * np + 0], alo, bh + 0);
                mma16816(acc[2 * np + 0], ahi, bl + 0);
                mma16816(acc[2 * np + 1], ahi, bh + 2);
                mma16816(acc[2 * np + 1], alo, bh + 2);
                mma16816(acc[2 * np + 1], ahi, bl + 2);
            }
        }

        // Epilogue 1 (registers only): H = lrelu(acc + b1a) repacked as GEMM2
        // A-fragments.  C(m16n8) regs {d0,d1;d2,d3} == A(m16k16) regs
        // {a0;a1} (j even -> k-lo) / {a2;a3} (j odd -> k-hi).
        uint32_t ah2[8][4], al2[8][4];
        #pragma unroll
        for (int j = 0; j < 16; ++j) {
            const int c = 8 * j + 2 * qt;
            const float bx = sb1a[c], by = sb1a[c + 1];
            uint16_t h0, l0, h1, l1, h2, l2, h3, l3;
            bf16_split(lrelu(acc[j][0] + bx), h0, l0);
            bf16_split(lrelu(acc[j][1] + by), h1, l1);
            bf16_split(lrelu(acc[j][2] + bx), h2, l2);
            bf16_split(lrelu(acc[j][3] + by), h3, l3);
            const int ks2 = j >> 1;
            const int ix = (j & 1) * 2;
            ah2[ks2][ix + 0] = (uint32_t)h0 | ((uint32_t)h1 << 16);
            ah2[ks2][ix + 1] = (uint32_t)h2 | ((uint32_t)h3 << 16);
            al2[ks2][ix + 0] = (uint32_t)l0 | ((uint32_t)l1 << 16);
            al2[ks2][ix + 1] = (uint32_t)l2 | ((uint32_t)l3 << 16);
        }

        // --- GEMM 2: A from registers, B = Wb planes ---
        #pragma unroll
        for (int j = 0; j < 16; ++j)
            #pragma unroll
            for (int q = 0; q < 4; ++q) acc[j][q] = 0.f;

        #pragma unroll
        for (int ks = 0; ks < 8; ++ks) {
            #pragma unroll
            for (int np = 0; np < 8; ++np) {
                uint32_t bh[4], bl[4];
                const uint32_t bb = (uint32_t)(ks * 16 * PADK + np * 16) * 2 + boff;
                ldsm4t(bh, wbhiA + bb);
                ldsm4t(bl, wbloA + bb);
                mma16816(acc[2 * np + 0], ah2[ks], bh + 0);
                mma16816(acc[2 * np + 0], al2[ks], bh + 0);
                mma16816(acc[2 * np + 0], ah2[ks], bl + 0);
                mma16816(acc[2 * np + 1], ah2[ks], bh + 2);
                mma16816(acc[2 * np + 1], al2[ks], bh + 2);
                mma16816(acc[2 * np + 1], ah2[ks], bl + 2);
            }
        }
        __syncthreads();   // all warps done reading V planes -> safe to overwrite with O

        // Stage O = acc + b1b into SMEM (fp32, row stride OPAD)
        {
            const int r = m0 + qr;
            #pragma unroll
            for (int j = 0; j < 16; ++j) {
                const int c = 8 * j + 2 * qt;
                const float bx = sb1b[c], by = sb1b[c + 1];
                float2* p0 = reinterpret_cast<float2*>(Ost + r * OPAD + c);
                float2* p1 = reinterpret_cast<float2*>(Ost + (r + 8) * OPAD + c);
                *p0 = make_float2(acc[j][0] + bx, acc[j][1] + by);
                *p1 = make_float2(acc[j][2] + bx, acc[j][3] + by);
            }
        }
        __syncthreads();

        // Scatter: 2 threads per row, red.v4, row-contiguous
        {
            const int r = tid >> 1;
            const int h = tid & 1;
            const int t = s_tgt[r];
            if (t >= 0) {
                float* gp = g_accum + (size_t)t * 128 + h * 64;
                const float4* op = reinterpret_cast<const float4*>(Ost + r * OPAD + h * 64);
                #pragma unroll
                for (int q = 0; q < 16; ++q) {
                    float4 v = op[q];
                    red_add_v4(gp + 4 * q, v.x, v.y, v.z, v.w);
                }
            }
        }
    }
}

// ---------------------------------------------------------------------------
// Node kernel (unchanged from passing R5/R8 version)
// ---------------------------------------------------------------------------
#define NT   32
#define NTH  256
#define NO_W    0
#define NO_IN   40960
#define NO_B2A  51200
#define NO_B2B  51328
#define NO_IDX  51456
#define N_SMEM_BYTES ((51456 + NT) * 4)

__global__ void __launch_bounds__(NTH, 1)
node_kernel(const float* __restrict__ x_g,
            const float* __restrict__ u,
            const float* __restrict__ W2a, const float* __restrict__ b2a,
            const float* __restrict__ W2b, const float* __restrict__ b2b,
            const int* __restrict__ batch_g,
            float* __restrict__ out, int NG)
{
    extern __shared__ float sm[];
    float* Wt   = sm + NO_W;
    float* IN   = sm + NO_IN;
    float* sb2a = sm + NO_B2A;
    float* sb2b = sm + NO_B2B;
    int*   s_b  = reinterpret_cast<int*>(sm + NO_IDX);

    const int tid = threadIdx.x;
    const int n0 = blockIdx.x * NT;

    for (int t = tid; t < 128 * 320; t += NTH) {
        int j = t / 320, k = t % 320;
        Wt[k * 128 + j] = W2a[t];
    }
    if (tid < 128) { sb2a[tid] = b2a[tid]; sb2b[tid] = b2b[tid]; }
    if (tid < NT) {
        int n = n0 + tid;
        int b = 0;
        if (n < NG) {
            b = batch_g[n];
            if (b < 0) b = 0;
            if (b > 15) b = 15;
        }
        s_b[tid] = b;
    }
    __syncthreads();

    float4* IN4 = reinterpret_cast<float4*>(IN);
    const float4* Wt4 = reinterpret_cast<const float4*>(Wt);

    for (int f = tid; f < NT * 80; f += NTH) {
        int i = f / 80, c = f % 80;
        int n = n0 + i;
        float4 val = make_float4(0.f, 0.f, 0.f, 0.f);
        if (n < NG) {
            if (c < 32)
                val = reinterpret_cast<const float4*>(x_g)[(size_t)n * 32 + c];
            else if (c < 64)
                val = reinterpret_cast<const float4*>(g_accum)[(size_t)n * 32 + (c - 32)];
            else
                val = reinterpret_cast<const float4*>(u)[(size_t)s_b[i] * 16 + (c - 64)];
        }
        IN4[f] = val;
    }
    __syncthreads();

    const int w = tid >> 5;
    const int l = tid & 31;
    const int i0 = w * 4;
    const float4 ba = reinterpret_cast<const float4*>(sb2a)[l];
    const float4 bb = reinterpret_cast<const float4*>(sb2b)[l];

    float4 acc[4];
    #pragma unroll
    for (int i = 0; i < 4; ++i) acc[i] = ba;

    for (int k4 = 0; k4 < 80; ++k4) {
        float4 w0 = Wt4[(k4 * 4 + 0) * 32 + l];
        float4 w1 = Wt4[(k4 * 4 + 1) * 32 + l];
        float4 w2 = Wt4[(k4 * 4 + 2) * 32 + l];
        float4 w3 = Wt4[(k4 * 4 + 3) * 32 + l];
        #pragma unroll
        for (int i = 0; i < 4; ++i) {
            float4 v = IN4[(i0 + i) * 80 + k4];
            acc[i].x = fmaf(v.x, w0.x, acc[i].x); acc[i].y = fmaf(v.x, w0.y, acc[i].y);
            acc[i].z = fmaf(v.x, w0.z, acc[i].z); acc[i].w = fmaf(v.x, w0.w, acc[i].w);
            acc[i].x = fmaf(v.y, w1.x, acc[i].x); acc[i].y = fmaf(v.y, w1.y, acc[i].y);
            acc[i].z = fmaf(v.y, w1.z, acc[i].z); acc[i].w = fmaf(v.y, w1.w, acc[i].w);
            acc[i].x = fmaf(v.z, w2.x, acc[i].x); acc[i].y = fmaf(v.z, w2.y, acc[i].y);
            acc[i].z = fmaf(v.z, w2.z, acc[i].z); acc[i].w = fmaf(v.z, w2.w, acc[i].w);
            acc[i].x = fmaf(v.w, w3.x, acc[i].x); acc[i].y = fmaf(v.w, w3.y, acc[i].y);
            acc[i].z = fmaf(v.w, w3.z, acc[i].z); acc[i].w = fmaf(v.w, w3.w, acc[i].w);
        }
    }

    __syncwarp();
    #pragma unroll
    for (int i = 0; i < 4; ++i) {
        float4 h;
        h.x = lrelu(acc[i].x); h.y = lrelu(acc[i].y);
        h.z = lrelu(acc[i].z); h.w = lrelu(acc[i].w);
        IN4[(i0 + i) * 80 + l] = h;
    }
    __syncthreads();

    for (int t = tid; t < 128 * 128; t += NTH) {
        int j = t >> 7, k = t & 127;
        Wt[k * 128 + j] = W2b[t];
    }
    __syncthreads();

    #pragma unroll
    for (int i = 0; i < 4; ++i) acc[i] = bb;

    for (int k4 = 0; k4 < 32; ++k4) {
        float4 w0 = Wt4[(k4 * 4 + 0) * 32 + l];
        float4 w1 = Wt4[(k4 * 4 + 1) * 32 + l];
        float4 w2 = Wt4[(k4 * 4 + 2) * 32 + l];
        float4 w3 = Wt4[(k4 * 4 + 3) * 32 + l];
        #pragma unroll
        for (int i = 0; i < 4; ++i) {
            float4 v = IN4[(i0 + i) * 80 + k4];
            acc[i].x = fmaf(v.x, w0.x, acc[i].x); acc[i].y = fmaf(v.x, w0.y, acc[i].y);
            acc[i].z = fmaf(v.x, w0.z, acc[i].z); acc[i].w = fmaf(v.x, w0.w, acc[i].w);
            acc[i].x = fmaf(v.y, w1.x, acc[i].x); acc[i].y = fmaf(v.y, w1.y, acc[i].y);
            acc[i].z = fmaf(v.y, w1.z, acc[i].z); acc[i].w = fmaf(v.y, w1.w, acc[i].w);
            acc[i].x = fmaf(v.z, w2.x, acc[i].x); acc[i].y = fmaf(v.z, w2.y, acc[i].y);
            acc[i].z = fmaf(v.z, w2.z, acc[i].z); acc[i].w = fmaf(v.z, w2.w, acc[i].w);
            acc[i].x = fmaf(v.w, w3.x, acc[i].x); acc[i].y = fmaf(v.w, w3.y, acc[i].y);
            acc[i].z = fmaf(v.w, w3.z, acc[i].z); acc[i].w = fmaf(v.w, w3.w, acc[i].w);
        }
    }

    #pragma unroll
    for (int i = 0; i < 4; ++i) {
        int n = n0 + i0 + i;
        if (n < NG)
            reinterpret_cast<float4*>(out)[(size_t)n * 32 + l] = acc[i];
    }
}

// ---------------------------------------------------------------------------
// kernel_launch
// Inputs: 0 x_h, 1 x_g, 2 edge_attr, 3 u, 4 W1a, 5 b1a, 6 W1b, 7 b1b,
//         8 W2a, 9 b2a, 10 W2b, 11 b2b, 12 edge_index (int32), 13 batch_g (int32)
// ---------------------------------------------------------------------------
extern "C" void kernel_launch(void* const* d_in, const int* in_sizes, int n_in,
                              void* d_out, int out_size) {
    const float* x_h       = (const float*)d_in[0];
    const float* x_g       = (const float*)d_in[1];
    const float* edge_attr = (const float*)d_in[2];
    const float* u         = (const float*)d_in[3];
    const float* W1a       = (const float*)d_in[4];
    const float* b1a       = (const float*)d_in[5];
    const float* W1b       = (const float*)d_in[6];
    const float* b1b       = (const float*)d_in[7];
    const float* W2a       = (const float*)d_in[8];
    const float* b2a       = (const float*)d_in[9];
    const float* W2b       = (const float*)d_in[10];
    const float* b2b       = (const float*)d_in[11];
    const int* eidx        = (const int*)d_in[12];
    const int* batch       = (const int*)d_in[13];
    float* out = (float*)d_out;

    const int E  = in_sizes[12] / 2;
    const int NG = in_sizes[1] / N_GC;

    cudaFuncSetAttribute(edge_kernel, cudaFuncAttributeMaxDynamicSharedMemorySize,
                         E_SMEM_BYTES);
    cudaFuncSetAttribute(node_kernel, cudaFuncAttributeMaxDynamicSharedMemorySize,
                         N_SMEM_BYTES);

    zero_accum_kernel<<<1024, 256>>>();
    edge_kernel<<<152, ETH, E_SMEM_BYTES>>>(x_h, edge_attr, W1a, b1a, W1b, b1b,
                                            eidx, E);
    int node_blocks = (NG + NT - 1) / NT;
    node_kernel<<<node_blocks, NTH, N_SMEM_BYTES>>>(x_g, u, W2a, b2a, W2b, b2b,
                                                    batch, out, NG);
}